// round 2
// baseline (speedup 1.0000x reference)
#include <cuda_runtime.h>
#include <cuda_bf16.h>
#include <stdint.h>

// Problem constants (fixed shapes for this problem)
#define MAXN 100000
#define MAXE 800000
#define DIM  128

// Scratch (device globals — no allocation allowed)
__device__ float g_h[(size_t)MAXN * DIM];    // hidden activations
__device__ float g_agg[(size_t)MAXN * DIM];  // scatter-add accumulator
__device__ float g_deg[MAXN];                // degree -> reciprocal degree
__device__ int   g_row[MAXE];                // normalized int32 dst indices
__device__ int   g_col[MAXE];                // normalized int32 src indices
__device__ int   g_is32;                     // 1 if edge_index buffer is int32

// ---------------------------------------------------------------------------
// Edge-index dtype probe + normalization
// If buffer is int64 (values < 2^31), every element's high 32-bit word is 0.
// If buffer is int32, the probed words are random indices (mostly nonzero).
// We probe words [2i+1] for i in [0,E) — in-bounds for BOTH interpretations.
// ---------------------------------------------------------------------------
__global__ void probe_kernel(const unsigned* __restrict__ w, int E, int* __restrict__ flag) {
    int i = blockIdx.x * blockDim.x + threadIdx.x;
    if (i == 0 && blockIdx.x == 0) { /* no-op */ }
    if (i < E) {
        if (w[2 * i + 1] != 0u) atomicOr(flag, 1);
    }
}

__global__ void convert_kernel(const void* __restrict__ ei,
                               int* __restrict__ row, int* __restrict__ col,
                               int E, const int* __restrict__ flag) {
    int i = blockIdx.x * blockDim.x + threadIdx.x;
    if (i >= E) return;
    if (*flag) {  // int32 layout: [row[0..E), col[0..E)]
        const int* p = (const int*)ei;
        row[i] = p[i];
        col[i] = p[E + i];
    } else {      // int64 layout
        const long long* p = (const long long*)ei;
        row[i] = (int)p[i];
        col[i] = (int)p[E + i];
    }
}

// ---------------------------------------------------------------------------
// Utility kernels
// ---------------------------------------------------------------------------
__global__ void zero_f4_kernel(float4* __restrict__ p, int n4) {
    int i = blockIdx.x * blockDim.x + threadIdx.x;
    if (i < n4) p[i] = make_float4(0.f, 0.f, 0.f, 0.f);
}

__global__ void zero_kernels_combo(float* __restrict__ deg, int n, int* __restrict__ flag) {
    int i = blockIdx.x * blockDim.x + threadIdx.x;
    if (i < n) deg[i] = 0.f;
    if (i == 0) *flag = 0;
}

__global__ void deg_kernel(const int* __restrict__ row, float* __restrict__ deg, int E) {
    int e = blockIdx.x * blockDim.x + threadIdx.x;
    if (e < E) atomicAdd(&deg[row[e]], 1.0f);
}

__global__ void rdeg_kernel(float* __restrict__ deg, int n) {
    int i = blockIdx.x * blockDim.x + threadIdx.x;
    if (i < n) deg[i] = 1.0f / fmaxf(deg[i], 1.0f);
}

// ---------------------------------------------------------------------------
// Scatter-add over edges: agg[row[e]] += h[col[e]]  (128 floats per edge)
// One warp per edge; each lane handles 4 floats via vectorized red.global.
// ---------------------------------------------------------------------------
__global__ __launch_bounds__(256) void scatter_kernel(
    const float* __restrict__ h,
    const int* __restrict__ row,
    const int* __restrict__ col,
    float* __restrict__ agg,
    int E)
{
    int e = blockIdx.x * 8 + (threadIdx.x >> 5);
    if (e >= E) return;
    int lane = threadIdx.x & 31;
    long long s = col[e];
    long long d = row[e];

    float4 v = __ldg((const float4*)(h + s * DIM) + lane);
    float* dst = agg + d * DIM + lane * 4;
    asm volatile("red.global.add.v4.f32 [%0], {%1, %2, %3, %4};"
                 :: "l"(dst), "f"(v.x), "f"(v.y), "f"(v.z), "f"(v.w)
                 : "memory");
}

// ---------------------------------------------------------------------------
// SGEMM: out[M,128] = transform(A)[M,128] @ W[128,128]^T + bias
// transform (layers 2,3): a = relu(A[m][k] * rdeg[m])   (mean + ReLU fused)
// BM=128, BN=128(full), BK=16, 256 threads, 8x8 register microtiles.
// ---------------------------------------------------------------------------
template <bool TRANSFORM>
__global__ __launch_bounds__(256) void gemm_kernel(
    const float* __restrict__ A,
    const float* __restrict__ W,
    const float* __restrict__ bias,
    const float* __restrict__ rdeg,
    float* __restrict__ out,
    int M)
{
    __shared__ float As[16][128];
    __shared__ float Bs[16][128];

    const int tid = threadIdx.x;
    const int m0  = blockIdx.x * 128;
    const int tx  = tid & 15;   // n-tile index (8 cols each)
    const int ty  = tid >> 4;   // m-tile index (8 rows each)

    const int lr = tid >> 2;          // 0..63 (row within tile for loads)
    const int lc = (tid & 3) * 4;     // 0,4,8,12 (k-offset for float4 load)

    float acc[8][8];
    #pragma unroll
    for (int i = 0; i < 8; ++i)
        #pragma unroll
        for (int j = 0; j < 8; ++j) acc[i][j] = 0.f;

    for (int k0 = 0; k0 < 128; k0 += 16) {
        // --- load A tile (transposed into As[k][m]) with optional transform ---
        #pragma unroll
        for (int p = 0; p < 2; ++p) {
            int r = lr + p * 64;
            int m = m0 + r;
            float4 v = make_float4(0.f, 0.f, 0.f, 0.f);
            if (m < M) {
                v = __ldg((const float4*)(A + (size_t)m * DIM + k0 + lc));
                if (TRANSFORM) {
                    float rd = __ldg(rdeg + m);
                    v.x = fmaxf(v.x * rd, 0.f);
                    v.y = fmaxf(v.y * rd, 0.f);
                    v.z = fmaxf(v.z * rd, 0.f);
                    v.w = fmaxf(v.w * rd, 0.f);
                }
            }
            As[lc + 0][r] = v.x;
            As[lc + 1][r] = v.y;
            As[lc + 2][r] = v.z;
            As[lc + 3][r] = v.w;
        }
        // --- load W tile (transposed into Bs[k][n]) ---
        #pragma unroll
        for (int p = 0; p < 2; ++p) {
            int n = lr + p * 64;
            float4 v = __ldg((const float4*)(W + (size_t)n * DIM + k0 + lc));
            Bs[lc + 0][n] = v.x;
            Bs[lc + 1][n] = v.y;
            Bs[lc + 2][n] = v.z;
            Bs[lc + 3][n] = v.w;
        }
        __syncthreads();

        #pragma unroll
        for (int kk = 0; kk < 16; ++kk) {
            float a[8], b[8];
            *(float4*)(a)     = *(const float4*)&As[kk][ty * 8];
            *(float4*)(a + 4) = *(const float4*)&As[kk][ty * 8 + 4];
            *(float4*)(b)     = *(const float4*)&Bs[kk][tx * 8];
            *(float4*)(b + 4) = *(const float4*)&Bs[kk][tx * 8 + 4];
            #pragma unroll
            for (int i = 0; i < 8; ++i)
                #pragma unroll
                for (int j = 0; j < 8; ++j)
                    acc[i][j] += a[i] * b[j];
        }
        __syncthreads();
    }

    // --- epilogue: add bias, store ---
    float bv[8];
    #pragma unroll
    for (int j = 0; j < 8; ++j) bv[j] = __ldg(bias + tx * 8 + j);

    #pragma unroll
    for (int i = 0; i < 8; ++i) {
        int m = m0 + ty * 8 + i;
        if (m < M) {
            float4 o0 = make_float4(acc[i][0] + bv[0], acc[i][1] + bv[1],
                                    acc[i][2] + bv[2], acc[i][3] + bv[3]);
            float4 o1 = make_float4(acc[i][4] + bv[4], acc[i][5] + bv[5],
                                    acc[i][6] + bv[6], acc[i][7] + bv[7]);
            float* o = out + (size_t)m * DIM + tx * 8;
            *(float4*)(o)     = o0;
            *(float4*)(o + 4) = o1;
        }
    }
}

// ---------------------------------------------------------------------------
// kernel_launch
// Inputs: x[N*128], edge_index[2*E], W1[128*128], b1[128],
//         W2[128*128], b2[128], W3[128*128], b3[128]
// ---------------------------------------------------------------------------
extern "C" void kernel_launch(void* const* d_in, const int* in_sizes, int n_in,
                              void* d_out, int out_size)
{
    const float* x   = (const float*)d_in[0];
    const void*  ei  = d_in[1];
    const float* W1  = (const float*)d_in[2];
    const float* b1  = (const float*)d_in[3];
    const float* W2  = (const float*)d_in[4];
    const float* b2  = (const float*)d_in[5];
    const float* W3  = (const float*)d_in[6];
    const float* b3  = (const float*)d_in[7];
    float*       out = (float*)d_out;

    const int N = in_sizes[0] / DIM;
    const int E = in_sizes[1] / 2;

    float* h;    cudaGetSymbolAddress((void**)&h,    g_h);
    float* agg;  cudaGetSymbolAddress((void**)&agg,  g_agg);
    float* deg;  cudaGetSymbolAddress((void**)&deg,  g_deg);
    int*   row;  cudaGetSymbolAddress((void**)&row,  g_row);
    int*   col;  cudaGetSymbolAddress((void**)&col,  g_col);
    int*   flag; cudaGetSymbolAddress((void**)&flag, g_is32);

    const int n4    = N * DIM / 4;
    const int zgrid = (n4 + 255) / 256;
    const int egrid = (E + 255) / 256;
    const int ngrid = (N + 255) / 256;
    const int sgrid = (E + 7) / 8;    // 8 edges (warps) per 256-thr block
    const int ggrid = (N + 127) / 128;

    // 0) dtype probe + normalize edge indices to int32 (also zeroes deg & flag)
    zero_kernels_combo<<<ngrid, 256>>>(deg, N, flag);
    probe_kernel<<<egrid, 256>>>((const unsigned*)ei, E, flag);
    convert_kernel<<<egrid, 256>>>(ei, row, col, E, flag);

    // 1) degree -> reciprocal (clamped)
    deg_kernel<<<egrid, 256>>>(row, deg, E);
    rdeg_kernel<<<ngrid, 256>>>(deg, N);

    // 2) layer 1: h = x @ W1^T + b1
    gemm_kernel<false><<<ggrid, 256>>>(x, W1, b1, nullptr, h, N);

    // 3) mp 1: agg = scatter_add(h[col] -> row)
    zero_f4_kernel<<<zgrid, 256>>>((float4*)agg, n4);
    scatter_kernel<<<sgrid, 256>>>(h, row, col, agg, E);

    // 4) layer 2: h = relu(agg * rdeg) @ W2^T + b2  (mean+relu fused into load)
    gemm_kernel<true><<<ggrid, 256>>>(agg, W2, b2, deg, h, N);

    // 5) mp 2
    zero_f4_kernel<<<zgrid, 256>>>((float4*)agg, n4);
    scatter_kernel<<<sgrid, 256>>>(h, row, col, agg, E);

    // 6) layer 3: out = relu(agg * rdeg) @ W3^T + b3
    gemm_kernel<true><<<ggrid, 256>>>(agg, W3, b3, deg, out, N);
}

// round 3
// speedup vs baseline: 1.3137x; 1.3137x over previous
#include <cuda_runtime.h>
#include <cuda_bf16.h>
#include <stdint.h>

// Problem constants (fixed shapes for this problem)
#define MAXN 100000
#define MAXE 800000
#define DIM  128

// Scratch (device globals — no allocation allowed)
__device__ float g_h[(size_t)MAXN * DIM];    // hidden activations
__device__ float g_agg[(size_t)MAXN * DIM];  // aggregated (mean+relu) activations
__device__ float g_rdeg[MAXN];               // reciprocal clamped degree
__device__ int   g_row[MAXE];                // normalized int32 dst indices
__device__ int   g_col[MAXE];                // normalized int32 src indices
__device__ int   g_cnt[MAXN];                // in-degree counts
__device__ int   g_offs[MAXN];               // CSR start offsets (exclusive scan)
__device__ int   g_cursor[MAXN];             // fill cursors
__device__ int   g_srcs[MAXE];               // CSR: source node per slot
__device__ int   g_bsum[1024];               // block sums for scan
__device__ int   g_is32;                     // 1 if edge_index buffer is int32

// ---------------------------------------------------------------------------
// Edge-index dtype probe: if buffer is int64 (values < 2^31), all high words
// are zero; if int32, probed words are random indices (mostly nonzero).
// ---------------------------------------------------------------------------
__global__ void probe_kernel(const unsigned* __restrict__ w, int E, int* __restrict__ flag) {
    int i = blockIdx.x * blockDim.x + threadIdx.x;
    if (i < E) {
        if (w[2 * i + 1] != 0u) atomicOr(flag, 1);
    }
}

// Normalize to int32 row/col + count in-degrees in the same pass.
__global__ void convert_count_kernel(const void* __restrict__ ei,
                                     int* __restrict__ row, int* __restrict__ col,
                                     int* __restrict__ cnt,
                                     int E, const int* __restrict__ flag) {
    int i = blockIdx.x * blockDim.x + threadIdx.x;
    if (i >= E) return;
    int r, c;
    if (*flag) {  // int32 layout: [row[0..E), col[0..E)]
        const int* p = (const int*)ei;
        r = p[i];
        c = p[E + i];
    } else {      // int64 layout
        const long long* p = (const long long*)ei;
        r = (int)p[i];
        c = (int)p[E + i];
    }
    row[i] = r;
    col[i] = c;
    atomicAdd(&cnt[r], 1);
}

__global__ void zero_init_kernel(int* __restrict__ cnt, int n, int* __restrict__ flag) {
    int i = blockIdx.x * blockDim.x + threadIdx.x;
    if (i < n) cnt[i] = 0;
    if (i == 0 && blockIdx.x == 0) *flag = 0;
}

// ---------------------------------------------------------------------------
// 3-kernel exclusive scan over cnt (n <= 1024*1024)
// ---------------------------------------------------------------------------
__global__ void scan1_kernel(const int* __restrict__ cnt, int* __restrict__ offs,
                             int* __restrict__ bsum, int n) {
    __shared__ int sh[1024];
    int i = blockIdx.x * 1024 + threadIdx.x;
    int v = (i < n) ? cnt[i] : 0;
    sh[threadIdx.x] = v;
    __syncthreads();
    #pragma unroll
    for (int d = 1; d < 1024; d <<= 1) {
        int t = (threadIdx.x >= d) ? sh[threadIdx.x - d] : 0;
        __syncthreads();
        sh[threadIdx.x] += t;
        __syncthreads();
    }
    if (i < n) offs[i] = sh[threadIdx.x] - v;   // exclusive within block
    if (threadIdx.x == 1023) bsum[blockIdx.x] = sh[1023];
}

__global__ void scan2_kernel(int* __restrict__ bsum, int nb) {
    __shared__ int sh[1024];
    int v = (threadIdx.x < nb) ? bsum[threadIdx.x] : 0;
    sh[threadIdx.x] = v;
    __syncthreads();
    #pragma unroll
    for (int d = 1; d < 1024; d <<= 1) {
        int t = (threadIdx.x >= d) ? sh[threadIdx.x - d] : 0;
        __syncthreads();
        sh[threadIdx.x] += t;
        __syncthreads();
    }
    if (threadIdx.x < nb) bsum[threadIdx.x] = sh[threadIdx.x] - v;  // exclusive
}

__global__ void scan3_kernel(int* __restrict__ offs, const int* __restrict__ bsum,
                             const int* __restrict__ cnt, int* __restrict__ cursor,
                             float* __restrict__ rdeg, int n) {
    int i = blockIdx.x * blockDim.x + threadIdx.x;
    if (i >= n) return;
    int o = offs[i] + bsum[i >> 10];
    offs[i] = o;
    cursor[i] = o;
    rdeg[i] = 1.0f / fmaxf((float)cnt[i], 1.0f);
}

__global__ void fill_kernel(const int* __restrict__ row, const int* __restrict__ col,
                            int* __restrict__ cursor, int* __restrict__ srcs, int E) {
    int e = blockIdx.x * blockDim.x + threadIdx.x;
    if (e >= E) return;
    int idx = atomicAdd(&cursor[row[e]], 1);
    srcs[idx] = col[e];
}

// ---------------------------------------------------------------------------
// Pull-mode aggregate: out[n] = relu( (sum_{s in N_in(n)} h[s]) * rdeg[n] )
// One warp per node, each lane owns 4 floats (float4). No atomics, coalesced
// writes. Unrolled by 2 for memory-level parallelism on the gathered rows.
// ---------------------------------------------------------------------------
__global__ __launch_bounds__(256) void aggregate_kernel(
    const float* __restrict__ h,
    const int* __restrict__ offs,
    const int* __restrict__ cnt,
    const int* __restrict__ srcs,
    const float* __restrict__ rdeg,
    float* __restrict__ out,
    int N)
{
    int node = blockIdx.x * 8 + (threadIdx.x >> 5);
    if (node >= N) return;
    int lane = threadIdx.x & 31;

    int start = __ldg(offs + node);
    int c     = __ldg(cnt + node);

    float4 acc = make_float4(0.f, 0.f, 0.f, 0.f);
    int j = 0;
    for (; j + 2 <= c; j += 2) {
        int s0 = __ldg(srcs + start + j);
        int s1 = __ldg(srcs + start + j + 1);
        float4 v0 = __ldg((const float4*)(h + (size_t)s0 * DIM) + lane);
        float4 v1 = __ldg((const float4*)(h + (size_t)s1 * DIM) + lane);
        acc.x += v0.x + v1.x;
        acc.y += v0.y + v1.y;
        acc.z += v0.z + v1.z;
        acc.w += v0.w + v1.w;
    }
    if (j < c) {
        int s0 = __ldg(srcs + start + j);
        float4 v0 = __ldg((const float4*)(h + (size_t)s0 * DIM) + lane);
        acc.x += v0.x;
        acc.y += v0.y;
        acc.z += v0.z;
        acc.w += v0.w;
    }

    float rd = __ldg(rdeg + node);
    float4 o;
    o.x = fmaxf(acc.x * rd, 0.f);
    o.y = fmaxf(acc.y * rd, 0.f);
    o.z = fmaxf(acc.z * rd, 0.f);
    o.w = fmaxf(acc.w * rd, 0.f);
    *((float4*)(out + (size_t)node * DIM) + lane) = o;
}

// ---------------------------------------------------------------------------
// SGEMM: out[M,128] = A[M,128] @ W[128,128]^T + bias
// BM=128, BN=128(full), BK=16, 256 threads, 8x8 register microtiles.
// ---------------------------------------------------------------------------
__global__ __launch_bounds__(256) void gemm_kernel(
    const float* __restrict__ A,
    const float* __restrict__ W,
    const float* __restrict__ bias,
    float* __restrict__ out,
    int M)
{
    __shared__ float As[16][128];
    __shared__ float Bs[16][128];

    const int tid = threadIdx.x;
    const int m0  = blockIdx.x * 128;
    const int tx  = tid & 15;   // n-tile index (8 cols each)
    const int ty  = tid >> 4;   // m-tile index (8 rows each)

    const int lr = tid >> 2;          // 0..63 (row within tile for loads)
    const int lc = (tid & 3) * 4;     // 0,4,8,12 (k-offset for float4 load)

    float acc[8][8];
    #pragma unroll
    for (int i = 0; i < 8; ++i)
        #pragma unroll
        for (int j = 0; j < 8; ++j) acc[i][j] = 0.f;

    for (int k0 = 0; k0 < 128; k0 += 16) {
        // --- load A tile (transposed into As[k][m]) ---
        #pragma unroll
        for (int p = 0; p < 2; ++p) {
            int r = lr + p * 64;
            int m = m0 + r;
            float4 v = make_float4(0.f, 0.f, 0.f, 0.f);
            if (m < M) {
                v = __ldg((const float4*)(A + (size_t)m * DIM + k0 + lc));
            }
            As[lc + 0][r] = v.x;
            As[lc + 1][r] = v.y;
            As[lc + 2][r] = v.z;
            As[lc + 3][r] = v.w;
        }
        // --- load W tile (transposed into Bs[k][n]) ---
        #pragma unroll
        for (int p = 0; p < 2; ++p) {
            int n = lr + p * 64;
            float4 v = __ldg((const float4*)(W + (size_t)n * DIM + k0 + lc));
            Bs[lc + 0][n] = v.x;
            Bs[lc + 1][n] = v.y;
            Bs[lc + 2][n] = v.z;
            Bs[lc + 3][n] = v.w;
        }
        __syncthreads();

        #pragma unroll
        for (int kk = 0; kk < 16; ++kk) {
            float a[8], b[8];
            *(float4*)(a)     = *(const float4*)&As[kk][ty * 8];
            *(float4*)(a + 4) = *(const float4*)&As[kk][ty * 8 + 4];
            *(float4*)(b)     = *(const float4*)&Bs[kk][tx * 8];
            *(float4*)(b + 4) = *(const float4*)&Bs[kk][tx * 8 + 4];
            #pragma unroll
            for (int i = 0; i < 8; ++i)
                #pragma unroll
                for (int j = 0; j < 8; ++j)
                    acc[i][j] += a[i] * b[j];
        }
        __syncthreads();
    }

    // --- epilogue: add bias, store ---
    float bv[8];
    #pragma unroll
    for (int j = 0; j < 8; ++j) bv[j] = __ldg(bias + tx * 8 + j);

    #pragma unroll
    for (int i = 0; i < 8; ++i) {
        int m = m0 + ty * 8 + i;
        if (m < M) {
            float4 o0 = make_float4(acc[i][0] + bv[0], acc[i][1] + bv[1],
                                    acc[i][2] + bv[2], acc[i][3] + bv[3]);
            float4 o1 = make_float4(acc[i][4] + bv[4], acc[i][5] + bv[5],
                                    acc[i][6] + bv[6], acc[i][7] + bv[7]);
            float* o = out + (size_t)m * DIM + tx * 8;
            *(float4*)(o)     = o0;
            *(float4*)(o + 4) = o1;
        }
    }
}

// ---------------------------------------------------------------------------
// kernel_launch
// Inputs: x[N*128], edge_index[2*E], W1[128*128], b1[128],
//         W2[128*128], b2[128], W3[128*128], b3[128]
// ---------------------------------------------------------------------------
extern "C" void kernel_launch(void* const* d_in, const int* in_sizes, int n_in,
                              void* d_out, int out_size)
{
    const float* x   = (const float*)d_in[0];
    const void*  ei  = d_in[1];
    const float* W1  = (const float*)d_in[2];
    const float* b1  = (const float*)d_in[3];
    const float* W2  = (const float*)d_in[4];
    const float* b2  = (const float*)d_in[5];
    const float* W3  = (const float*)d_in[6];
    const float* b3  = (const float*)d_in[7];
    float*       out = (float*)d_out;

    const int N = in_sizes[0] / DIM;
    const int E = in_sizes[1] / 2;

    float* h;      cudaGetSymbolAddress((void**)&h,      g_h);
    float* agg;    cudaGetSymbolAddress((void**)&agg,    g_agg);
    float* rdeg;   cudaGetSymbolAddress((void**)&rdeg,   g_rdeg);
    int*   row;    cudaGetSymbolAddress((void**)&row,    g_row);
    int*   col;    cudaGetSymbolAddress((void**)&col,    g_col);
    int*   cnt;    cudaGetSymbolAddress((void**)&cnt,    g_cnt);
    int*   offs;   cudaGetSymbolAddress((void**)&offs,   g_offs);
    int*   cursor; cudaGetSymbolAddress((void**)&cursor, g_cursor);
    int*   srcs;   cudaGetSymbolAddress((void**)&srcs,   g_srcs);
    int*   bsum;   cudaGetSymbolAddress((void**)&bsum,   g_bsum);
    int*   flag;   cudaGetSymbolAddress((void**)&flag,   g_is32);

    const int egrid = (E + 255) / 256;
    const int ngrid = (N + 255) / 256;
    const int nb    = (N + 1023) / 1024;   // scan blocks
    const int wgrid = (N + 7) / 8;         // 8 node-warps per 256-thr block
    const int ggrid = (N + 127) / 128;

    // 0) dtype probe + normalize edge indices + count in-degrees
    zero_init_kernel<<<ngrid, 256>>>(cnt, N, flag);
    probe_kernel<<<egrid, 256>>>((const unsigned*)ei, E, flag);
    convert_count_kernel<<<egrid, 256>>>(ei, row, col, cnt, E, flag);

    // 1) CSR build: exclusive scan + fill
    scan1_kernel<<<nb, 1024>>>(cnt, offs, bsum, N);
    scan2_kernel<<<1, 1024>>>(bsum, nb);
    scan3_kernel<<<ngrid, 256>>>(offs, bsum, cnt, cursor, rdeg, N);
    fill_kernel<<<egrid, 256>>>(row, col, cursor, srcs, E);

    // 2) layer 1: h = x @ W1^T + b1
    gemm_kernel<<<ggrid, 256>>>(x, W1, b1, h, N);

    // 3) mp 1: agg = relu(mean of in-neighbors of h)   (pull-mode, no atomics)
    aggregate_kernel<<<wgrid, 256>>>(h, offs, cnt, srcs, rdeg, agg, N);

    // 4) layer 2: h = agg @ W2^T + b2
    gemm_kernel<<<ggrid, 256>>>(agg, W2, b2, h, N);

    // 5) mp 2
    aggregate_kernel<<<wgrid, 256>>>(h, offs, cnt, srcs, rdeg, agg, N);

    // 6) layer 3: out = agg @ W3^T + b3
    gemm_kernel<<<ggrid, 256>>>(agg, W3, b3, out, N);
}